// round 9
// baseline (speedup 1.0000x reference)
#include <cuda_runtime.h>
#include <cuda_fp16.h>
#include <cstdint>
#include <math.h>

#define HID    1024
#define INTER  4096
#define NTOK   4096
#define NKEYS  64
#define TOPK   8

typedef unsigned short u16;
typedef unsigned int   u32;

// ---------------- scratch (no allocations allowed) ----------------
__device__ __align__(16) static u16   g_Xh[(size_t)NTOK * HID];
__device__ __align__(16) static u16   g_Xl[(size_t)NTOK * HID];   // kept (unused now) for layout stability
__device__ __align__(16) static u16   g_Wgh[(size_t)INTER * HID];
__device__ __align__(16) static u16   g_Wuh[(size_t)INTER * HID];
__device__ __align__(16) static u16   g_Wdh[(size_t)HID * INTER];
__device__ __align__(16) static u16   g_Hh[(size_t)NTOK * INTER];
__device__ static int   g_tidx[NTOK * TOPK];
__device__ static float g_tw[NTOK * TOPK];
__device__ static u32   g_ctr;

// ---------------- helpers ----------------
__device__ __forceinline__ u32 smem_u32(const void* p) {
    u32 a;
    asm("{ .reg .u64 t; cvta.to.shared.u64 t, %1; cvt.u32.u64 %0, t; }" : "=r"(a) : "l"(p));
    return a;
}

__device__ __forceinline__ void cp16(u32 dst, const void* src) {
    asm volatile("cp.async.cg.shared.global [%0], [%1], 16;" :: "r"(dst), "l"(src));
}
#define CP_COMMIT() asm volatile("cp.async.commit_group;" ::: "memory")
#define CP_WAIT(n)  asm volatile("cp.async.wait_group %0;" :: "n"(n) : "memory")

__device__ __forceinline__ void ldsm_x4(u32& r0, u32& r1, u32& r2, u32& r3, u32 addr) {
    asm volatile("ldmatrix.sync.aligned.m8n8.x4.shared.b16 {%0,%1,%2,%3}, [%4];"
                 : "=r"(r0), "=r"(r1), "=r"(r2), "=r"(r3) : "r"(addr));
}
__device__ __forceinline__ void ldsm_x2(u32& r0, u32& r1, u32 addr) {
    asm volatile("ldmatrix.sync.aligned.m8n8.x2.shared.b16 {%0,%1}, [%2];"
                 : "=r"(r0), "=r"(r1) : "r"(addr));
}

__device__ __forceinline__ void mma_f32(float* c, const u32* a, const u32* b) {
    asm volatile(
        "mma.sync.aligned.m16n8k16.row.col.f32.f16.f16.f32 "
        "{%0,%1,%2,%3}, {%4,%5,%6,%7}, {%8,%9}, {%0,%1,%2,%3};"
        : "+f"(c[0]), "+f"(c[1]), "+f"(c[2]), "+f"(c[3])
        : "r"(a[0]), "r"(a[1]), "r"(a[2]), "r"(a[3]), "r"(b[0]), "r"(b[1]));
}

__device__ __forceinline__ float silu(float x) { return x / (1.f + expf(-x)); }

// =====================================================================
// prep_kernel: grid 8448.
//  bid < 256   : router tile (exact fp32 SIMT) -> logits
//  bid >= 256  : fp32->fp16 conversions (X split2; Wg/Wu/Wd split1)
// =====================================================================
__global__ __launch_bounds__(256)
void prep_kernel(const float* __restrict__ X,
                 const float* __restrict__ Wr,
                 const float* __restrict__ Wg,
                 const float* __restrict__ Wu,
                 const float* __restrict__ Wd,
                 u16* __restrict__ Xh,
                 u16* __restrict__ Wgh, u16* __restrict__ Wuh,
                 u16* __restrict__ Wdh,
                 float* __restrict__ logits)
{
    const int b = blockIdx.x;
    const int tid = threadIdx.x;

    if (b < 256) {
        // router: 64(M) x 32(N) tile; thread owns 2 rows x 4 cols
        const int rx = b & 63, ry = b >> 6;
        const int r0 = rx * 64 + (tid >> 3) * 2;
        const int c0 = ry * 32 + (tid & 7) * 4;
        const float* a0 = X + (size_t)r0 * HID;
        const float* a1 = a0 + HID;
        const float* b0 = Wr + (size_t)c0 * HID;
        float acc[2][4] = {};
        for (int k = 0; k < HID; k += 4) {
            float4 va0 = *(const float4*)(a0 + k);
            float4 va1 = *(const float4*)(a1 + k);
            #pragma unroll
            for (int j = 0; j < 4; j++) {
                float4 vb = *(const float4*)(b0 + (size_t)j * HID + k);
                acc[0][j] += va0.x * vb.x + va0.y * vb.y + va0.z * vb.z + va0.w * vb.w;
                acc[1][j] += va1.x * vb.x + va1.y * vb.y + va1.z * vb.z + va1.w * vb.w;
            }
        }
        #pragma unroll
        for (int i = 0; i < 2; i++)
            #pragma unroll
            for (int j = 0; j < 4; j++)
                logits[(size_t)(r0 + i) * 128 + c0 + j] = acc[i][j];
        return;
    }

    const int sb = b - 256;
    const int region = sb >> 11;          // 2048 blocks per region
    const int blk = sb & 2047;
    const int i0 = blk * 512 + tid;       // two float4s: i0, i0+256

    if (region == 0) {
        // X split2
        #pragma unroll
        for (int t = 0; t < 2; t++) {
            int i = i0 + t * 256;
            float4 v = ((const float4*)X)[i];
            __half hx = __float2half_rn(v.x), hy = __float2half_rn(v.y);
            __half hz = __float2half_rn(v.z), hw = __float2half_rn(v.w);
            __half lx = __float2half_rn(v.x - __half2float(hx));
            __half ly = __float2half_rn(v.y - __half2float(hy));
            __half lz = __float2half_rn(v.z - __half2float(hz));
            __half lw = __float2half_rn(v.w - __half2float(hw));
            __half2 h0 = __halves2half2(hx, hy), h1 = __halves2half2(hz, hw);
            __half2 l0 = __halves2half2(lx, ly), l1 = __halves2half2(lz, lw);
            ((uint2*)Xh)[i]       = make_uint2(*(u32*)&h0, *(u32*)&h1);
            ((uint2*)g_Xl)[i]     = make_uint2(*(u32*)&l0, *(u32*)&l1);
        }
    } else {
        const float* src = (region == 1) ? Wg : (region == 2) ? Wu : Wd;
        u16* dst = (region == 1) ? Wgh : (region == 2) ? Wuh : Wdh;
        #pragma unroll
        for (int t = 0; t < 2; t++) {
            int i = i0 + t * 256;
            float4 v = ((const float4*)src)[i];
            __half2 h0 = __halves2half2(__float2half_rn(v.x), __float2half_rn(v.y));
            __half2 h1 = __halves2half2(__float2half_rn(v.z), __float2half_rn(v.w));
            ((uint2*)dst)[i] = make_uint2(*(u32*)&h0, *(u32*)&h1);
        }
    }
}

#define PITCH 80
#define PLANE128 10240                // 128 rows * 80
#define PLANE64  5120                 // 64 rows * 80

// =====================================================================
// mlp1_kernel: grid (32, 64), 256 thr, occ 2. CTA tile 128(M)x64(N).
// fused gate/up — Hh = f16(silu(X@Wg^T) * (X@Wu^T)). BK=32, 3-stage.
// =====================================================================
#define STG_GU 20480
#define SMEM_MLP1 61440

__global__ __launch_bounds__(256, 2)
void mlp1_kernel(const u16* __restrict__ Xh,
                 const u16* __restrict__ Wgh, const u16* __restrict__ Wuh,
                 u16* __restrict__ Hh)
{
    extern __shared__ char sm[];
    const u32 sb = smem_u32(sm);
    const int tid  = threadIdx.x;
    const int lane = tid & 31;
    const int wid  = tid >> 5;
    const int row0 = blockIdx.x * 128;
    const int col0 = blockIdx.y * 64;
    const int warpM = (wid & 3) * 32;
    const int warpN = (wid >> 2) * 32;

    const int lrA = tid >> 1;
    const int cA  = (tid & 1) * 2;
    const int lrB = tid >> 2;
    const int cB  = tid & 3;

    const int l4 = lane & 15;
    const u32 aRowOff = (u32)((lane & 15) * PITCH + ((lane >> 4) << 4));
    const u32 bRowOff = (u32)((l4 & 7) * PITCH + ((l4 >> 3) << 4));

    const int NS = HID >> 5;

    auto load_stage = [&](int kt, int buf) {
        const u32 so = sb + buf * STG_GU;
        const size_t goA = (size_t)(row0 + lrA) * HID + kt * 32;
        cp16(so + lrA * PITCH + cA * 16,       Xh + goA + cA * 8);
        cp16(so + lrA * PITCH + (cA + 1) * 16, Xh + goA + (cA + 1) * 8);
        const size_t goB = (size_t)(col0 + lrB) * HID + kt * 32;
        cp16(so + PLANE128 + lrB * PITCH + cB * 16,            Wgh + goB + cB * 8);
        cp16(so + PLANE128 + PLANE64 + lrB * PITCH + cB * 16,  Wuh + goB + cB * 8);
    };

    float accG[2][4][4], accU[2][4][4];
    #pragma unroll
    for (int i = 0; i < 2; i++)
        #pragma unroll
        for (int j = 0; j < 4; j++)
            #pragma unroll
            for (int t = 0; t < 4; t++) { accG[i][j][t] = 0.f; accU[i][j][t] = 0.f; }

    load_stage(0, 0); CP_COMMIT();
    load_stage(1, 1); CP_COMMIT();

    for (int s = 0; s < NS; s++) {
        const int buf = s % 3;
        CP_WAIT(1);
        __syncthreads();
        if (s + 2 < NS) load_stage(s + 2, (s + 2) % 3);
        CP_COMMIT();

        const u32 stg = sb + buf * STG_GU;
        #pragma unroll
        for (int ks = 0; ks < 2; ks++) {
            const u32 kb = ks * 32;
            u32 ah[2][4], bg[4][2], bu[4][2];
            #pragma unroll
            for (int i = 0; i < 2; i++)
                ldsm_x4(ah[i][0], ah[i][1], ah[i][2], ah[i][3],
                        stg + (warpM + i * 16) * PITCH + kb + aRowOff);
            #pragma unroll
            for (int j = 0; j < 4; j++) {
                const u32 rb = stg + PLANE128 + (warpN + j * 8) * PITCH + kb + bRowOff;
                ldsm_x2(bg[j][0], bg[j][1], rb);
                ldsm_x2(bu[j][0], bu[j][1], rb + PLANE64);
            }
            #pragma unroll
            for (int i = 0; i < 2; i++)
                #pragma unroll
                for (int j = 0; j < 4; j++) {
                    mma_f32(accG[i][j], ah[i], bg[j]);
                    mma_f32(accU[i][j], ah[i], bu[j]);
                }
        }
    }

    #pragma unroll
    for (int i = 0; i < 2; i++) {
        #pragma unroll
        for (int j = 0; j < 4; j++) {
            const int r = row0 + warpM + i * 16 + (lane >> 2);
            const int c = col0 + warpN + j * 8 + (lane & 3) * 2;
            #pragma unroll
            for (int half = 0; half < 2; half++) {
                const int rr = r + half * 8;
                const float gg0 = accG[i][j][half * 2 + 0];
                const float gg1 = accG[i][j][half * 2 + 1];
                const float uu0 = accU[i][j][half * 2 + 0];
                const float uu1 = accU[i][j][half * 2 + 1];
                __half2 hp = __halves2half2(__float2half_rn(silu(gg0) * uu0),
                                            __float2half_rn(silu(gg1) * uu1));
                ((u32*)Hh)[((size_t)rr * INTER + c) >> 1] = *(u32*)&hp;
            }
        }
    }
}

// =====================================================================
// routing_zero_kernel: grid 4096. Zeros out; blocks [0,16) route;
// block 0 thread 0 also resets the down work counter.
// =====================================================================
__device__ __forceinline__ void top8_insert(float v, int idx, float* hv, int* hi) {
    if (v <= hv[7]) return;
    int p = 7;
    #pragma unroll
    for (int q = 7; q > 0; q--) {
        if (v > hv[q-1]) { hv[q] = hv[q-1]; hi[q] = hi[q-1]; p = q - 1; }
    }
    hv[p] = v; hi[p] = idx;
}

__global__ void routing_zero_kernel(const float* __restrict__ logits,
                                    float* __restrict__ out)
{
    const int b = blockIdx.x;
    const int tid = threadIdx.x;
    ((float4*)out)[b * 256 + tid] = make_float4(0.f, 0.f, 0.f, 0.f);
    if (b == 0 && tid == 0) g_ctr = 0u;
    if (b >= 16) return;

    const int m = b * 256 + tid;
    const float* px = logits + (size_t)(m >> 1) * 128 + (m & 1) * 64;
    const float* py = logits + (size_t)(2048 + (m >> 1)) * 128 + (m & 1) * 64;

    float vx[8], vy[8];
    int   ix[8], iy[8];
    #pragma unroll
    for (int t = 0; t < 8; t++) { vx[t] = -3.4e38f; vy[t] = -3.4e38f; ix[t] = 0; iy[t] = 0; }
    for (int k = 0; k < NKEYS; k++) top8_insert(px[k], k, vx, ix);
    for (int k = 0; k < NKEYS; k++) top8_insert(py[k], k, vy, iy);

    float sv[8]; int sa[8];
    #pragma unroll
    for (int t = 0; t < 8; t++) { sv[t] = -3.4e38f; sa[t] = 0; }
    for (int a = 0; a < 8; a++)
        for (int bq = 0; bq < 8; bq++)
            top8_insert(vx[a] + vy[bq], a * 8 + bq, sv, sa);

    float mx = sv[0];
    float e[8], s = 0.f;
    #pragma unroll
    for (int t = 0; t < 8; t++) { e[t] = expf(sv[t] - mx); s += e[t]; }
    float w[8], s2 = 0.f;
    #pragma unroll
    for (int t = 0; t < 8; t++) { w[t] = e[t] / s; s2 += w[t]; }
    #pragma unroll
    for (int t = 0; t < 8; t++) w[t] /= s2;

    #pragma unroll
    for (int t = 0; t < 8; t++) {
        int a = sa[t] >> 3, bq = sa[t] & 7;
        g_tidx[m * TOPK + t] = ix[a] * NKEYS + iy[bq];
        g_tw[m * TOPK + t]   = w[t];
    }
}

// =====================================================================
// tail_kernel: grid 296 + 4096, occ 3 (256 thr, <=85 regs).
//  bid < 296 : persistent down-GEMM worker. Work items from g_ctr:
//              item in [0,1024): tile 128x64, K-half 2048 (64 stages).
//              atomicAdd epilogue.
//  bid >= 296: experts token (atomicAdd) — runs in the 3rd CTA slot,
//              fully hidden under down's tensor time.
// =====================================================================
#define STG_D  15360                  // (128+64)*80
#define SMEM_TAIL (3 * STG_D + 128)   // 46208

__global__ __launch_bounds__(256, 3)
void tail_kernel(const u16* __restrict__ A_h, const u16* __restrict__ B_h,
                 float* __restrict__ out,
                 const float* __restrict__ X,
                 const float* __restrict__ down_e,
                 const float* __restrict__ up_e)
{
    extern __shared__ char sm[];
    const int tid = threadIdx.x;

    if (blockIdx.x < 296) {
        // ---------------- persistent down worker ----------------
        const u32 sb = smem_u32(sm);
        u32* itemBox = (u32*)(sm + 3 * STG_D);
        const int lane = tid & 31;
        const int wid  = tid >> 5;
        const int warpM = (wid & 3) * 32;
        const int warpN = (wid >> 2) * 32;

        const int lrA = tid >> 1;
        const int cA  = (tid & 1) * 2;
        const int lrB = tid >> 2;
        const int cB  = tid & 3;

        const int l4 = lane & 15;
        const u32 aRowOff = (u32)((lane & 15) * PITCH + ((lane >> 4) << 4));
        const u32 bRowOff = (u32)((l4 & 7) * PITCH + ((l4 >> 3) << 4));

        for (;;) {
            if (tid == 0) *itemBox = atomicAdd(&g_ctr, 1u);
            CP_WAIT(0);
            __syncthreads();
            const u32 item = *itemBox;
            if (item >= 1024u) break;

            const int tileId = item >> 1;
            const int kbase  = (item & 1) * 2048;
            const int row0 = (tileId & 31) * 128;
            const int col0 = (tileId >> 5) * 64;

            auto load_stage = [&](int kt, int buf) {
                const u32 so = sb + buf * STG_D;
                const size_t goA = (size_t)(row0 + lrA) * INTER + kbase + kt * 32;
                cp16(so + lrA * PITCH + cA * 16,       A_h + goA + cA * 8);
                cp16(so + lrA * PITCH + (cA + 1) * 16, A_h + goA + (cA + 1) * 8);
                const size_t goB = (size_t)(col0 + lrB) * INTER + kbase + kt * 32;
                cp16(so + PLANE128 + lrB * PITCH + cB * 16, B_h + goB + cB * 8);
            };

            float acc[2][4][4];
            #pragma unroll
            for (int i = 0; i < 2; i++)
                #pragma unroll
                for (int j = 0; j < 4; j++)
                    #pragma unroll
                    for (int t = 0; t < 4; t++) acc[i][j][t] = 0.f;

            load_stage(0, 0); CP_COMMIT();
            load_stage(1, 1); CP_COMMIT();

            const int NS = 64;
            for (int s = 0; s < NS; s++) {
                const int buf = s % 3;
                CP_WAIT(1);
                __syncthreads();
                if (s + 2 < NS) load_stage(s + 2, (s + 2) % 3);
                CP_COMMIT();

                const u32 stg = sb + buf * STG_D;
                #pragma unroll
                for (int ks = 0; ks < 2; ks++) {
                    const u32 kb = ks * 32;
                    u32 ah[2][4], bh[4][2];
                    #pragma unroll
                    for (int i = 0; i < 2; i++)
                        ldsm_x4(ah[i][0], ah[i][1], ah[i][2], ah[i][3],
                                stg + (warpM + i * 16) * PITCH + kb + aRowOff);
                    #pragma unroll
                    for (int j = 0; j < 4; j++)
                        ldsm_x2(bh[j][0], bh[j][1],
                                stg + PLANE128 + (warpN + j * 8) * PITCH + kb + bRowOff);
                    #pragma unroll
                    for (int i = 0; i < 2; i++)
                        #pragma unroll
                        for (int j = 0; j < 4; j++) mma_f32(acc[i][j], ah[i], bh[j]);
                }
            }

            #pragma unroll
            for (int i = 0; i < 2; i++) {
                #pragma unroll
                for (int j = 0; j < 4; j++) {
                    const int r = row0 + warpM + i * 16 + (lane >> 2);
                    const int c = col0 + warpN + j * 8 + (lane & 3) * 2;
                    #pragma unroll
                    for (int half = 0; half < 2; half++) {
                        const int rr = r + half * 8;
                        atomicAdd(out + (size_t)rr * HID + c,     acc[i][j][half * 2 + 0]);
                        atomicAdd(out + (size_t)rr * HID + c + 1, acc[i][j][half * 2 + 1]);
                    }
                }
            }
            __syncthreads();
        }
    } else {
        // ---------------- experts token ----------------
        const int m = blockIdx.x - 296;
        float4* xs4 = (float4*)sm;
        float*  ews = (float*)(sm + 4096);

        xs4[tid] = ((const float4*)(X + (size_t)m * HID))[tid];
        __syncthreads();

        const float* xs = (const float*)xs4;
        const int wid  = tid >> 5;
        const int lane = tid & 31;

        {
            int e = g_tidx[m * TOPK + wid];
            const float* d = down_e + (size_t)e * HID;
            float s = 0.f;
            for (int k = lane; k < HID; k += 32) s = fmaf(d[k], xs[k], s);
            #pragma unroll
            for (int o = 16; o; o >>= 1) s += __shfl_xor_sync(0xffffffffu, s, o);
            if (lane == 0) {
                float sig = s / (1.f + expf(-s));
                ews[wid] = sig * g_tw[m * TOPK + wid];
            }
        }
        __syncthreads();

        float4 acc = make_float4(0.f, 0.f, 0.f, 0.f);
        #pragma unroll
        for (int k = 0; k < TOPK; k++) {
            int e = g_tidx[m * TOPK + k];
            float w = ews[k];
            float4 u = ((const float4*)(up_e + (size_t)e * HID))[tid];
            acc.x = fmaf(w, u.x, acc.x);
            acc.y = fmaf(w, u.y, acc.y);
            acc.z = fmaf(w, u.z, acc.z);
            acc.w = fmaf(w, u.w, acc.w);
        }
        float* dst = out + (size_t)m * HID + tid * 4;
        atomicAdd(dst + 0, acc.x);
        atomicAdd(dst + 1, acc.y);
        atomicAdd(dst + 2, acc.z);
        atomicAdd(dst + 3, acc.w);
    }
}

// ---------------- launch ----------------
static void* sym(const void* s) { void* p = nullptr; cudaGetSymbolAddress(&p, s); return p; }

extern "C" void kernel_launch(void* const* d_in, const int* in_sizes, int n_in,
                              void* d_out, int out_size)
{
    const float* X        = (const float*)d_in[0];
    const float* w_gate   = (const float*)d_in[1];
    const float* w_up     = (const float*)d_in[2];
    const float* w_down   = (const float*)d_in[3];
    const float* w_router = (const float*)d_in[4];
    const float* down_e   = (const float*)d_in[5];
    const float* up_e     = (const float*)d_in[6];

    float* out    = (float*)d_out;
    float* logits = (float*)d_out + (size_t)NTOK * HID;

    u16 *Xh = (u16*)sym(g_Xh);
    u16 *Wgh = (u16*)sym(g_Wgh);
    u16 *Wuh = (u16*)sym(g_Wuh);
    u16 *Wdh = (u16*)sym(g_Wdh);
    u16 *Hh = (u16*)sym(g_Hh);

    cudaFuncSetAttribute(mlp1_kernel, cudaFuncAttributeMaxDynamicSharedMemorySize, SMEM_MLP1);
    cudaFuncSetAttribute(tail_kernel, cudaFuncAttributeMaxDynamicSharedMemorySize, SMEM_TAIL);

    // 0) router (exact fp32) + all splits, one launch
    prep_kernel<<<8448, 256>>>(X, w_router, w_gate, w_up, w_down,
                               Xh, Wgh, Wuh, Wdh, logits);
    // 1) routing top-k + zero out + reset work counter
    routing_zero_kernel<<<4096, 256>>>(logits, out);
    // 2) fused gate/up
    mlp1_kernel<<<dim3(NTOK / 128, INTER / 64), 256, SMEM_MLP1>>>(Xh, Wgh, Wuh, Hh);
    // 3) persistent down GEMM + experts (occ 3; experts hidden under down)
    tail_kernel<<<296 + NTOK, 256, SMEM_TAIL>>>(Hh, Wdh, out, X, down_e, up_e);
    (void)in_sizes; (void)n_in; (void)out_size;
}

// round 10
// speedup vs baseline: 1.6429x; 1.6429x over previous
#include <cuda_runtime.h>
#include <cuda_fp16.h>
#include <cstdint>
#include <math.h>

#define HID    1024
#define INTER  4096
#define NTOK   4096
#define NKEYS  64
#define TOPK   8

typedef unsigned short u16;
typedef unsigned int   u32;

// ---------------- scratch (no allocations allowed) ----------------
__device__ __align__(16) static u16   g_Xh[(size_t)NTOK * HID];
__device__ __align__(16) static u16   g_Xl[(size_t)NTOK * HID];
__device__ __align__(16) static u16   g_Wgh[(size_t)INTER * HID];
__device__ __align__(16) static u16   g_Wuh[(size_t)INTER * HID];
__device__ __align__(16) static u16   g_Wdh[(size_t)HID * INTER];
__device__ __align__(16) static u16   g_Wrh[(size_t)128 * HID];
__device__ __align__(16) static u16   g_Wrl[(size_t)128 * HID];
__device__ __align__(16) static u16   g_Hh[(size_t)NTOK * INTER];
__device__ static int   g_tidx[NTOK * TOPK];
__device__ static float g_tw[NTOK * TOPK];

// ---------------- helpers ----------------
__device__ __forceinline__ u32 smem_u32(const void* p) {
    u32 a;
    asm("{ .reg .u64 t; cvta.to.shared.u64 t, %1; cvt.u32.u64 %0, t; }" : "=r"(a) : "l"(p));
    return a;
}

__device__ __forceinline__ void cp16(u32 dst, const void* src) {
    asm volatile("cp.async.cg.shared.global [%0], [%1], 16;" :: "r"(dst), "l"(src));
}
#define CP_COMMIT() asm volatile("cp.async.commit_group;" ::: "memory")
#define CP_WAIT(n)  asm volatile("cp.async.wait_group %0;" :: "n"(n) : "memory")

__device__ __forceinline__ void ldsm_x4(u32& r0, u32& r1, u32& r2, u32& r3, u32 addr) {
    asm volatile("ldmatrix.sync.aligned.m8n8.x4.shared.b16 {%0,%1,%2,%3}, [%4];"
                 : "=r"(r0), "=r"(r1), "=r"(r2), "=r"(r3) : "r"(addr));
}
__device__ __forceinline__ void ldsm_x2(u32& r0, u32& r1, u32 addr) {
    asm volatile("ldmatrix.sync.aligned.m8n8.x2.shared.b16 {%0,%1}, [%2];"
                 : "=r"(r0), "=r"(r1) : "r"(addr));
}

__device__ __forceinline__ void mma_f32(float* c, const u32* a, const u32* b) {
    asm volatile(
        "mma.sync.aligned.m16n8k16.row.col.f32.f16.f16.f32 "
        "{%0,%1,%2,%3}, {%4,%5,%6,%7}, {%8,%9}, {%0,%1,%2,%3};"
        : "+f"(c[0]), "+f"(c[1]), "+f"(c[2]), "+f"(c[3])
        : "r"(a[0]), "r"(a[1]), "r"(a[2]), "r"(a[3]), "r"(b[0]), "r"(b[1]));
}
__device__ __forceinline__ void mma_f16(u32* c, const u32* a, const u32* b) {
    asm volatile(
        "mma.sync.aligned.m16n8k16.row.col.f16.f16.f16.f16 "
        "{%0,%1}, {%2,%3,%4,%5}, {%6,%7}, {%0,%1};"
        : "+r"(c[0]), "+r"(c[1])
        : "r"(a[0]), "r"(a[1]), "r"(a[2]), "r"(a[3]), "r"(b[0]), "r"(b[1]));
}

__device__ __forceinline__ float silu(float x) { return x / (1.f + expf(-x)); }

// =====================================================================
// fused split kernel: all fp32->fp16 conversions in one launch.
// blocks [0,4096): X split2 ; [4096,4224): Wr split2 ;
// [4224,8320): Wg ; [8320,12416): Wu ; [12416,16512): Wd (split1)
// =====================================================================
__global__ void split_all_kernel(const float* __restrict__ X,
                                 const float* __restrict__ Wr,
                                 const float* __restrict__ Wg,
                                 const float* __restrict__ Wu,
                                 const float* __restrict__ Wd,
                                 u16* __restrict__ Xh, u16* __restrict__ Xl,
                                 u16* __restrict__ Wrh, u16* __restrict__ Wrl,
                                 u16* __restrict__ Wgh, u16* __restrict__ Wuh,
                                 u16* __restrict__ Wdh)
{
    const int b = blockIdx.x;
    const int tid = threadIdx.x;
    if (b < 4224) {
        const float* src; u16 *hi, *lo; int i;
        if (b < 4096) { src = X;  hi = Xh;  lo = Xl;  i = b * 256 + tid; }
        else          { src = Wr; hi = Wrh; lo = Wrl; i = (b - 4096) * 256 + tid; }
        float4 v = ((const float4*)src)[i];
        __half hx = __float2half_rn(v.x), hy = __float2half_rn(v.y);
        __half hz = __float2half_rn(v.z), hw = __float2half_rn(v.w);
        __half lx = __float2half_rn(v.x - __half2float(hx));
        __half ly = __float2half_rn(v.y - __half2float(hy));
        __half lz = __float2half_rn(v.z - __half2float(hz));
        __half lw = __float2half_rn(v.w - __half2float(hw));
        __half2 h0 = __halves2half2(hx, hy), h1 = __halves2half2(hz, hw);
        __half2 l0 = __halves2half2(lx, ly), l1 = __halves2half2(lz, lw);
        ((uint2*)hi)[i] = make_uint2(*(u32*)&h0, *(u32*)&h1);
        ((uint2*)lo)[i] = make_uint2(*(u32*)&l0, *(u32*)&l1);
    } else {
        const float* src; u16* dst; int i;
        if (b < 8320)       { src = Wg; dst = Wgh; i = (b - 4224) * 256 + tid; }
        else if (b < 12416) { src = Wu; dst = Wuh; i = (b - 8320) * 256 + tid; }
        else                { src = Wd; dst = Wdh; i = (b - 12416) * 256 + tid; }
        float4 v = ((const float4*)src)[i];
        __half2 h0 = __halves2half2(__float2half_rn(v.x), __float2half_rn(v.y));
        __half2 h1 = __halves2half2(__float2half_rn(v.z), __float2half_rn(v.w));
        ((uint2*)dst)[i] = make_uint2(*(u32*)&h0, *(u32*)&h1);
    }
}

#define PITCH 80
#define PLANE128 10240                // 128 rows * 80
#define PLANE64  5120                 // 64 rows * 80

// =====================================================================
// mlp1_kernel: grid (32, 66), 256 thr, occ 2. CTA tile 128(M)x64(N).
//  y < 64 : fused gate/up — Hh = f16(silu(X@Wg^T) * (X@Wu^T))
//  y >= 64: router (fp16x3) — logits columns [(y-64)*64 .. +64)
// =====================================================================
#define STG_GU 20480
#define STG_R  30720
#define SMEM_MLP1 61440

__global__ __launch_bounds__(256, 2)
void mlp1_kernel(const u16* __restrict__ Xh, const u16* __restrict__ Xl,
                 const u16* __restrict__ Wgh, const u16* __restrict__ Wuh,
                 const u16* __restrict__ Wrh, const u16* __restrict__ Wrl,
                 u16* __restrict__ Hh, float* __restrict__ logits)
{
    extern __shared__ char sm[];
    const u32 sb = smem_u32(sm);
    const int tid  = threadIdx.x;
    const int lane = tid & 31;
    const int wid  = tid >> 5;
    const int row0 = blockIdx.x * 128;
    const int warpM = (wid & 3) * 32;
    const int warpN = (wid >> 2) * 32;

    const int lrA = tid >> 1;
    const int cA  = (tid & 1) * 2;
    const int lrB = tid >> 2;
    const int cB  = tid & 3;

    const int l4 = lane & 15;
    const u32 aRowOff = (u32)((lane & 15) * PITCH + ((lane >> 4) << 4));
    const u32 bRowOff = (u32)((l4 & 7) * PITCH + ((l4 >> 3) << 4));

    const int NS = HID >> 5;

    if (blockIdx.y < 64) {
        const int col0 = blockIdx.y * 64;

        auto load_stage = [&](int kt, int buf) {
            const u32 so = sb + buf * STG_GU;
            const size_t goA = (size_t)(row0 + lrA) * HID + kt * 32;
            cp16(so + lrA * PITCH + cA * 16,       Xh + goA + cA * 8);
            cp16(so + lrA * PITCH + (cA + 1) * 16, Xh + goA + (cA + 1) * 8);
            const size_t goB = (size_t)(col0 + lrB) * HID + kt * 32;
            cp16(so + PLANE128 + lrB * PITCH + cB * 16,            Wgh + goB + cB * 8);
            cp16(so + PLANE128 + PLANE64 + lrB * PITCH + cB * 16,  Wuh + goB + cB * 8);
        };

        float accG[2][4][4], accU[2][4][4];
        #pragma unroll
        for (int i = 0; i < 2; i++)
            #pragma unroll
            for (int j = 0; j < 4; j++)
                #pragma unroll
                for (int t = 0; t < 4; t++) { accG[i][j][t] = 0.f; accU[i][j][t] = 0.f; }

        load_stage(0, 0); CP_COMMIT();
        load_stage(1, 1); CP_COMMIT();

        for (int s = 0; s < NS; s++) {
            const int buf = s % 3;
            CP_WAIT(1);
            __syncthreads();
            if (s + 2 < NS) load_stage(s + 2, (s + 2) % 3);
            CP_COMMIT();

            const u32 stg = sb + buf * STG_GU;
            #pragma unroll
            for (int ks = 0; ks < 2; ks++) {
                const u32 kb = ks * 32;
                u32 ah[2][4], bg[4][2], bu[4][2];
                #pragma unroll
                for (int i = 0; i < 2; i++)
                    ldsm_x4(ah[i][0], ah[i][1], ah[i][2], ah[i][3],
                            stg + (warpM + i * 16) * PITCH + kb + aRowOff);
                #pragma unroll
                for (int j = 0; j < 4; j++) {
                    const u32 rb = stg + PLANE128 + (warpN + j * 8) * PITCH + kb + bRowOff;
                    ldsm_x2(bg[j][0], bg[j][1], rb);
                    ldsm_x2(bu[j][0], bu[j][1], rb + PLANE64);
                }
                #pragma unroll
                for (int i = 0; i < 2; i++)
                    #pragma unroll
                    for (int j = 0; j < 4; j++) {
                        mma_f32(accG[i][j], ah[i], bg[j]);
                        mma_f32(accU[i][j], ah[i], bu[j]);
                    }
            }
        }

        #pragma unroll
        for (int i = 0; i < 2; i++) {
            #pragma unroll
            for (int j = 0; j < 4; j++) {
                const int r = row0 + warpM + i * 16 + (lane >> 2);
                const int c = col0 + warpN + j * 8 + (lane & 3) * 2;
                #pragma unroll
                for (int half = 0; half < 2; half++) {
                    const int rr = r + half * 8;
                    const float gg0 = accG[i][j][half * 2 + 0];
                    const float gg1 = accG[i][j][half * 2 + 1];
                    const float uu0 = accU[i][j][half * 2 + 0];
                    const float uu1 = accU[i][j][half * 2 + 1];
                    __half2 hp = __halves2half2(__float2half_rn(silu(gg0) * uu0),
                                                __float2half_rn(silu(gg1) * uu1));
                    ((u32*)Hh)[((size_t)rr * INTER + c) >> 1] = *(u32*)&hp;
                }
            }
        }
    } else {
        const int col0 = (blockIdx.y - 64) * 64;

        auto load_stage = [&](int kt, int buf) {
            const u32 so = sb + buf * STG_R;
            const size_t goA = (size_t)(row0 + lrA) * HID + kt * 32;
            cp16(so + lrA * PITCH + cA * 16,                  Xh + goA + cA * 8);
            cp16(so + lrA * PITCH + (cA + 1) * 16,            Xh + goA + (cA + 1) * 8);
            cp16(so + PLANE128 + lrA * PITCH + cA * 16,       Xl + goA + cA * 8);
            cp16(so + PLANE128 + lrA * PITCH + (cA + 1) * 16, Xl + goA + (cA + 1) * 8);
            const size_t goB = (size_t)(col0 + lrB) * HID + kt * 32;
            cp16(so + 2 * PLANE128 + lrB * PITCH + cB * 16,           Wrh + goB + cB * 8);
            cp16(so + 2 * PLANE128 + PLANE64 + lrB * PITCH + cB * 16, Wrl + goB + cB * 8);
        };

        float acc[2][4][4];
        u32   accX[2][4][2];
        #pragma unroll
        for (int i = 0; i < 2; i++)
            #pragma unroll
            for (int j = 0; j < 4; j++) {
                #pragma unroll
                for (int t = 0; t < 4; t++) acc[i][j][t] = 0.f;
                accX[i][j][0] = 0u; accX[i][j][1] = 0u;
            }

        load_stage(0, 0); CP_COMMIT();

        for (int s = 0; s < NS; s++) {
            const int buf = s & 1;
            if (s + 1 < NS) load_stage(s + 1, (s + 1) & 1);
            CP_COMMIT();
            CP_WAIT(1);
            __syncthreads();

            const u32 stg = sb + buf * STG_R;
            #pragma unroll
            for (int ks = 0; ks < 2; ks++) {
                const u32 kb = ks * 32;
                u32 ah[2][4], al[2][4], bh[4][2], bl[4][2];
                #pragma unroll
                for (int i = 0; i < 2; i++) {
                    const u32 ra = stg + (warpM + i * 16) * PITCH + kb + aRowOff;
                    ldsm_x4(ah[i][0], ah[i][1], ah[i][2], ah[i][3], ra);
                    ldsm_x4(al[i][0], al[i][1], al[i][2], al[i][3], ra + PLANE128);
                }
                #pragma unroll
                for (int j = 0; j < 4; j++) {
                    const u32 rb = stg + 2 * PLANE128 + (warpN + j * 8) * PITCH + kb + bRowOff;
                    ldsm_x2(bh[j][0], bh[j][1], rb);
                    ldsm_x2(bl[j][0], bl[j][1], rb + PLANE64);
                }
                #pragma unroll
                for (int i = 0; i < 2; i++)
                    #pragma unroll
                    for (int j = 0; j < 4; j++) {
                        mma_f32(acc[i][j], ah[i], bh[j]);
                        mma_f16(accX[i][j], ah[i], bl[j]);
                        mma_f16(accX[i][j], al[i], bh[j]);
                    }
            }
            __syncthreads();
        }

        #pragma unroll
        for (int i = 0; i < 2; i++) {
            #pragma unroll
            for (int j = 0; j < 4; j++) {
                float2 x0 = __half22float2(*(__half2*)&accX[i][j][0]);
                float2 x1 = __half22float2(*(__half2*)&accX[i][j][1]);
                const float vv[4] = { acc[i][j][0] + x0.x, acc[i][j][1] + x0.y,
                                      acc[i][j][2] + x1.x, acc[i][j][3] + x1.y };
                const int r = row0 + warpM + i * 16 + (lane >> 2);
                const int c = col0 + warpN + j * 8 + (lane & 3) * 2;
                #pragma unroll
                for (int half = 0; half < 2; half++) {
                    const int rr = r + half * 8;
                    *(float2*)(logits + (size_t)rr * 128 + c) =
                        make_float2(vv[half * 2 + 0], vv[half * 2 + 1]);
                }
            }
        }
    }
}

// =====================================================================
// routing_zero_kernel: grid 4096. Every block zeros its 4KB slice of out;
// blocks [0,16) also compute routing for tokens [b*256, b*256+256).
// =====================================================================
__device__ __forceinline__ void top8_insert(float v, int idx, float* hv, int* hi) {
    if (v <= hv[7]) return;
    int p = 7;
    #pragma unroll
    for (int q = 7; q > 0; q--) {
        if (v > hv[q-1]) { hv[q] = hv[q-1]; hi[q] = hi[q-1]; p = q - 1; }
    }
    hv[p] = v; hi[p] = idx;
}

__global__ void routing_zero_kernel(const float* __restrict__ logits,
                                    float* __restrict__ out)
{
    const int b = blockIdx.x;
    const int tid = threadIdx.x;
    ((float4*)out)[b * 256 + tid] = make_float4(0.f, 0.f, 0.f, 0.f);
    if (b >= 16) return;

    const int m = b * 256 + tid;
    const float* px = logits + (size_t)(m >> 1) * 128 + (m & 1) * 64;
    const float* py = logits + (size_t)(2048 + (m >> 1)) * 128 + (m & 1) * 64;

    float vx[8], vy[8];
    int   ix[8], iy[8];
    #pragma unroll
    for (int t = 0; t < 8; t++) { vx[t] = -3.4e38f; vy[t] = -3.4e38f; ix[t] = 0; iy[t] = 0; }
    for (int k = 0; k < NKEYS; k++) top8_insert(px[k], k, vx, ix);
    for (int k = 0; k < NKEYS; k++) top8_insert(py[k], k, vy, iy);

    float sv[8]; int sa[8];
    #pragma unroll
    for (int t = 0; t < 8; t++) { sv[t] = -3.4e38f; sa[t] = 0; }
    for (int a = 0; a < 8; a++)
        for (int bq = 0; bq < 8; bq++)
            top8_insert(vx[a] + vy[bq], a * 8 + bq, sv, sa);

    float mx = sv[0];
    float e[8], s = 0.f;
    #pragma unroll
    for (int t = 0; t < 8; t++) { e[t] = expf(sv[t] - mx); s += e[t]; }
    float w[8], s2 = 0.f;
    #pragma unroll
    for (int t = 0; t < 8; t++) { w[t] = e[t] / s; s2 += w[t]; }
    #pragma unroll
    for (int t = 0; t < 8; t++) w[t] /= s2;

    #pragma unroll
    for (int t = 0; t < 8; t++) {
        int a = sa[t] >> 3, bq = sa[t] & 7;
        g_tidx[m * TOPK + t] = ix[a] * NKEYS + iy[bq];
        g_tw[m * TOPK + t]   = w[t];
    }
}

// =====================================================================
// tail_kernel: grid 1024 + 4096, occ 2.
//  bid < 1024 : down GEMM item — tile 128(M)x64(N), K-half (2048), static.
//               item = bid; tileId = bid>>1 (32 M x 16 N), kbase = (bid&1)*2048.
//               atomicAdd epilogue. ~18us granularity kills wave quantization.
//  bid >= 1024: experts token (atomicAdd epilogue), backfills.
// out pre-zeroed; fp add commutative -> deterministic.
// =====================================================================
#define STG_D  15360                  // (128+64)*80
#define SMEM_TAIL (3 * STG_D)         // 46080

__global__ __launch_bounds__(256, 2)
void tail_kernel(const u16* __restrict__ A_h, const u16* __restrict__ B_h,
                 float* __restrict__ out,
                 const float* __restrict__ X,
                 const float* __restrict__ down_e,
                 const float* __restrict__ up_e)
{
    extern __shared__ char sm[];
    const int tid = threadIdx.x;

    if (blockIdx.x < 1024) {
        // ---------------- down GEMM item ----------------
        const u32 sb = smem_u32(sm);
        const int lane = tid & 31;
        const int wid  = tid >> 5;
        const int warpM = (wid & 3) * 32;
        const int warpN = (wid >> 2) * 32;

        const int tileId = blockIdx.x >> 1;
        const int kbase  = (blockIdx.x & 1) * 2048;
        const int row0 = (tileId & 31) * 128;
        const int col0 = (tileId >> 5) * 64;

        const int lrA = tid >> 1;
        const int cA  = (tid & 1) * 2;
        const int lrB = tid >> 2;
        const int cB  = tid & 3;

        const int l4 = lane & 15;
        const u32 aRowOff = (u32)((lane & 15) * PITCH + ((lane >> 4) << 4));
        const u32 bRowOff = (u32)((l4 & 7) * PITCH + ((l4 >> 3) << 4));

        auto load_stage = [&](int kt, int buf) {
            const u32 so = sb + buf * STG_D;
            const size_t goA = (size_t)(row0 + lrA) * INTER + kbase + kt * 32;
            cp16(so + lrA * PITCH + cA * 16,       A_h + goA + cA * 8);
            cp16(so + lrA * PITCH + (cA + 1) * 16, A_h + goA + (cA + 1) * 8);
            const size_t goB = (size_t)(col0 + lrB) * INTER + kbase + kt * 32;
            cp16(so + PLANE128 + lrB * PITCH + cB * 16, B_h + goB + cB * 8);
        };

        float acc[2][4][4];
        #pragma unroll
        for (int i = 0; i < 2; i++)
            #pragma unroll
            for (int j = 0; j < 4; j++)
                #pragma unroll
                for (int t = 0; t < 4; t++) acc[i][j][t] = 0.f;

        load_stage(0, 0); CP_COMMIT();
        load_stage(1, 1); CP_COMMIT();

        const int NS = 64;
        for (int s = 0; s < NS; s++) {
            const int buf = s % 3;
            CP_WAIT(1);
            __syncthreads();
            if (s + 2 < NS) load_stage(s + 2, (s + 2) % 3);
            CP_COMMIT();

            const u32 stg = sb + buf * STG_D;
            #pragma unroll
            for (int ks = 0; ks < 2; ks++) {
                const u32 kb = ks * 32;
                u32 ah[2][4], bh[4][2];
                #pragma unroll
                for (int i = 0; i < 2; i++)
                    ldsm_x4(ah[i][0], ah[i][1], ah[i][2], ah[i][3],
                            stg + (warpM + i * 16) * PITCH + kb + aRowOff);
                #pragma unroll
                for (int j = 0; j < 4; j++)
                    ldsm_x2(bh[j][0], bh[j][1],
                            stg + PLANE128 + (warpN + j * 8) * PITCH + kb + bRowOff);
                #pragma unroll
                for (int i = 0; i < 2; i++)
                    #pragma unroll
                    for (int j = 0; j < 4; j++) mma_f32(acc[i][j], ah[i], bh[j]);
            }
        }

        #pragma unroll
        for (int i = 0; i < 2; i++) {
            #pragma unroll
            for (int j = 0; j < 4; j++) {
                const int r = row0 + warpM + i * 16 + (lane >> 2);
                const int c = col0 + warpN + j * 8 + (lane & 3) * 2;
                #pragma unroll
                for (int half = 0; half < 2; half++) {
                    const int rr = r + half * 8;
                    atomicAdd(out + (size_t)rr * HID + c,     acc[i][j][half * 2 + 0]);
                    atomicAdd(out + (size_t)rr * HID + c + 1, acc[i][j][half * 2 + 1]);
                }
            }
        }
    } else {
        // ---------------- experts token ----------------
        const int m = blockIdx.x - 1024;
        float4* xs4 = (float4*)sm;
        float*  ews = (float*)(sm + 4096);

        xs4[tid] = ((const float4*)(X + (size_t)m * HID))[tid];
        __syncthreads();

        const float* xs = (const float*)xs4;
        const int wid  = tid >> 5;
        const int lane = tid & 31;

        {
            int e = g_tidx[m * TOPK + wid];
            const float* d = down_e + (size_t)e * HID;
            float s = 0.f;
            for (int k = lane; k < HID; k += 32) s = fmaf(d[k], xs[k], s);
            #pragma unroll
            for (int o = 16; o; o >>= 1) s += __shfl_xor_sync(0xffffffffu, s, o);
            if (lane == 0) {
                float sig = s / (1.f + expf(-s));
                ews[wid] = sig * g_tw[m * TOPK + wid];
            }
        }
        __syncthreads();

        float4 acc = make_float4(0.f, 0.f, 0.f, 0.f);
        #pragma unroll
        for (int k = 0; k < TOPK; k++) {
            int e = g_tidx[m * TOPK + k];
            float w = ews[k];
            float4 u = ((const float4*)(up_e + (size_t)e * HID))[tid];
            acc.x = fmaf(w, u.x, acc.x);
            acc.y = fmaf(w, u.y, acc.y);
            acc.z = fmaf(w, u.z, acc.z);
            acc.w = fmaf(w, u.w, acc.w);
        }
        float* dst = out + (size_t)m * HID + tid * 4;
        atomicAdd(dst + 0, acc.x);
        atomicAdd(dst + 1, acc.y);
        atomicAdd(dst + 2, acc.z);
        atomicAdd(dst + 3, acc.w);
    }
}

// ---------------- launch ----------------
static void* sym(const void* s) { void* p = nullptr; cudaGetSymbolAddress(&p, s); return p; }

extern "C" void kernel_launch(void* const* d_in, const int* in_sizes, int n_in,
                              void* d_out, int out_size)
{
    const float* X        = (const float*)d_in[0];
    const float* w_gate   = (const float*)d_in[1];
    const float* w_up     = (const float*)d_in[2];
    const float* w_down   = (const float*)d_in[3];
    const float* w_router = (const float*)d_in[4];
    const float* down_e   = (const float*)d_in[5];
    const float* up_e     = (const float*)d_in[6];

    float* out    = (float*)d_out;
    float* logits = (float*)d_out + (size_t)NTOK * HID;

    u16 *Xh = (u16*)sym(g_Xh),  *Xl = (u16*)sym(g_Xl);
    u16 *Wgh = (u16*)sym(g_Wgh);
    u16 *Wuh = (u16*)sym(g_Wuh);
    u16 *Wdh = (u16*)sym(g_Wdh);
    u16 *Wrh = (u16*)sym(g_Wrh), *Wrl = (u16*)sym(g_Wrl);
    u16 *Hh = (u16*)sym(g_Hh);

    cudaFuncSetAttribute(mlp1_kernel, cudaFuncAttributeMaxDynamicSharedMemorySize, SMEM_MLP1);
    cudaFuncSetAttribute(tail_kernel, cudaFuncAttributeMaxDynamicSharedMemorySize, SMEM_TAIL);

    // 0) all splits, one launch
    split_all_kernel<<<16512, 256>>>(X, w_router, w_gate, w_up, w_down,
                                     Xh, Xl, Wrh, Wrl, Wgh, Wuh, Wdh);
    // 1) fused gate/up + router
    mlp1_kernel<<<dim3(NTOK / 128, 66), 256, SMEM_MLP1>>>(
        Xh, Xl, Wgh, Wuh, Wrh, Wrl, Hh, logits);
    // 2) routing top-k + zero out
    routing_zero_kernel<<<4096, 256>>>(logits, out);
    // 3) down GEMM (fine-grained static items) + experts, one launch
    tail_kernel<<<1024 + NTOK, 256, SMEM_TAIL>>>(Hh, Wdh, out, X, down_e, up_e);
    (void)in_sizes; (void)n_in; (void)out_size;
}

// round 12
// speedup vs baseline: 1.7565x; 1.0692x over previous
#include <cuda_runtime.h>
#include <cuda_fp16.h>
#include <cstdint>
#include <math.h>

#define HID    1024
#define INTER  4096
#define NTOK   4096
#define NKEYS  64
#define TOPK   8

typedef unsigned short u16;
typedef unsigned int   u32;

// ---------------- scratch (no allocations allowed) ----------------
__device__ __align__(16) static u16   g_Xh[(size_t)NTOK * HID];
__device__ __align__(16) static u16   g_Xl[(size_t)NTOK * HID];
__device__ __align__(16) static u16   g_Wgh[(size_t)INTER * HID];
__device__ __align__(16) static u16   g_Wuh[(size_t)INTER * HID];
__device__ __align__(16) static u16   g_Wdh[(size_t)HID * INTER];
__device__ __align__(16) static u16   g_Wrh[(size_t)128 * HID];
__device__ __align__(16) static u16   g_Wrl[(size_t)128 * HID];
__device__ __align__(16) static u16   g_Hh[(size_t)NTOK * INTER];
__device__ static int   g_tidx[NTOK * TOPK];
__device__ static float g_tw[NTOK * TOPK];

// ---------------- helpers ----------------
__device__ __forceinline__ u32 smem_u32(const void* p) {
    u32 a;
    asm("{ .reg .u64 t; cvta.to.shared.u64 t, %1; cvt.u32.u64 %0, t; }" : "=r"(a) : "l"(p));
    return a;
}

__device__ __forceinline__ void cp16(u32 dst, const void* src) {
    asm volatile("cp.async.cg.shared.global [%0], [%1], 16;" :: "r"(dst), "l"(src));
}
#define CP_COMMIT() asm volatile("cp.async.commit_group;" ::: "memory")
#define CP_WAIT(n)  asm volatile("cp.async.wait_group %0;" :: "n"(n) : "memory")

__device__ __forceinline__ void ldsm_x4(u32& r0, u32& r1, u32& r2, u32& r3, u32 addr) {
    asm volatile("ldmatrix.sync.aligned.m8n8.x4.shared.b16 {%0,%1,%2,%3}, [%4];"
                 : "=r"(r0), "=r"(r1), "=r"(r2), "=r"(r3) : "r"(addr));
}
__device__ __forceinline__ void ldsm_x2(u32& r0, u32& r1, u32 addr) {
    asm volatile("ldmatrix.sync.aligned.m8n8.x2.shared.b16 {%0,%1}, [%2];"
                 : "=r"(r0), "=r"(r1) : "r"(addr));
}

__device__ __forceinline__ void mma_f32(float* c, const u32* a, const u32* b) {
    asm volatile(
        "mma.sync.aligned.m16n8k16.row.col.f32.f16.f16.f32 "
        "{%0,%1,%2,%3}, {%4,%5,%6,%7}, {%8,%9}, {%0,%1,%2,%3};"
        : "+f"(c[0]), "+f"(c[1]), "+f"(c[2]), "+f"(c[3])
        : "r"(a[0]), "r"(a[1]), "r"(a[2]), "r"(a[3]), "r"(b[0]), "r"(b[1]));
}
__device__ __forceinline__ void mma_f16(u32* c, const u32* a, const u32* b) {
    asm volatile(
        "mma.sync.aligned.m16n8k16.row.col.f16.f16.f16.f16 "
        "{%0,%1}, {%2,%3,%4,%5}, {%6,%7}, {%0,%1};"
        : "+r"(c[0]), "+r"(c[1])
        : "r"(a[0]), "r"(a[1]), "r"(a[2]), "r"(a[3]), "r"(b[0]), "r"(b[1]));
}

__device__ __forceinline__ float silu(float x) { return x / (1.f + expf(-x)); }

// =====================================================================
// split_all_kernel: one launch.
// blocks [0,4096): X split2 ; [4096,4224): Wr split2 ;
// [4224,8320): Wg split1 ; [8320,12416): Wu split1 ;
// [12416,16512): zero `out` (4M floats).
// (Wd split rides under mlp1 where DRAM is idle.)
// =====================================================================
__global__ void split_all_kernel(const float* __restrict__ X,
                                 const float* __restrict__ Wr,
                                 const float* __restrict__ Wg,
                                 const float* __restrict__ Wu,
                                 u16* __restrict__ Xh, u16* __restrict__ Xl,
                                 u16* __restrict__ Wrh, u16* __restrict__ Wrl,
                                 u16* __restrict__ Wgh, u16* __restrict__ Wuh,
                                 float* __restrict__ out)
{
    const int b = blockIdx.x;
    const int tid = threadIdx.x;
    if (b < 4224) {
        const float* src; u16 *hi, *lo; int i;
        if (b < 4096) { src = X;  hi = Xh;  lo = Xl;  i = b * 256 + tid; }
        else          { src = Wr; hi = Wrh; lo = Wrl; i = (b - 4096) * 256 + tid; }
        float4 v = ((const float4*)src)[i];
        __half hx = __float2half_rn(v.x), hy = __float2half_rn(v.y);
        __half hz = __float2half_rn(v.z), hw = __float2half_rn(v.w);
        __half lx = __float2half_rn(v.x - __half2float(hx));
        __half ly = __float2half_rn(v.y - __half2float(hy));
        __half lz = __float2half_rn(v.z - __half2float(hz));
        __half lw = __float2half_rn(v.w - __half2float(hw));
        __half2 h0 = __halves2half2(hx, hy), h1 = __halves2half2(hz, hw);
        __half2 l0 = __halves2half2(lx, ly), l1 = __halves2half2(lz, lw);
        ((uint2*)hi)[i] = make_uint2(*(u32*)&h0, *(u32*)&h1);
        ((uint2*)lo)[i] = make_uint2(*(u32*)&l0, *(u32*)&l1);
    } else if (b < 12416) {
        const float* src; u16* dst; int i;
        if (b < 8320) { src = Wg; dst = Wgh; i = (b - 4224) * 256 + tid; }
        else          { src = Wu; dst = Wuh; i = (b - 8320) * 256 + tid; }
        float4 v = ((const float4*)src)[i];
        __half2 h0 = __halves2half2(__float2half_rn(v.x), __float2half_rn(v.y));
        __half2 h1 = __halves2half2(__float2half_rn(v.z), __float2half_rn(v.w));
        ((uint2*)dst)[i] = make_uint2(*(u32*)&h0, *(u32*)&h1);
    } else {
        ((float4*)out)[(b - 12416) * 256 + tid] = make_float4(0.f, 0.f, 0.f, 0.f);
    }
}

#define PITCH 80
#define PLANE128 10240                // 128 rows * 80
#define PLANE64  5120                 // 64 rows * 80

// =====================================================================
// mlp1_kernel: grid (32, 67), 256 thr, occ 2.
//  y == 0       : Wd fp32->fp16 split. Wd = 1,048,576 float4 total;
//                 32 CTAs x 128 iters x 256 thr = 1,048,576. (R11 bug:
//                 4x overrun trampled g_Hh — fixed constants here.)
//  y in [1,64]  : fused gate/up — Hh = f16(silu(X@Wg^T) * (X@Wu^T)),
//                 col0 = (y-1)*64. CTA tile 128(M)x64(N), BK=32, 3-stage.
//  y in [65,66] : router (fp16x3) — logits cols [(y-65)*64 .. +64)
// =====================================================================
#define STG_GU 20480
#define STG_R  30720
#define SMEM_MLP1 61440

__global__ __launch_bounds__(256, 2)
void mlp1_kernel(const u16* __restrict__ Xh, const u16* __restrict__ Xl,
                 const u16* __restrict__ Wgh, const u16* __restrict__ Wuh,
                 const u16* __restrict__ Wrh, const u16* __restrict__ Wrl,
                 const float* __restrict__ Wd, u16* __restrict__ Wdh,
                 u16* __restrict__ Hh, float* __restrict__ logits)
{
    extern __shared__ char sm[];
    const int tid  = threadIdx.x;

    if (blockIdx.y == 0) {
        // ---------------- Wd split: 32768 float4 per CTA ----------------
        const int base = blockIdx.x * 32768;
        #pragma unroll 4
        for (int t = 0; t < 128; t++) {
            const int i = base + t * 256 + tid;
            float4 v = ((const float4*)Wd)[i];
            __half2 h0 = __halves2half2(__float2half_rn(v.x), __float2half_rn(v.y));
            __half2 h1 = __halves2half2(__float2half_rn(v.z), __float2half_rn(v.w));
            ((uint2*)Wdh)[i] = make_uint2(*(u32*)&h0, *(u32*)&h1);
        }
        return;
    }

    const u32 sb = smem_u32(sm);
    const int lane = tid & 31;
    const int wid  = tid >> 5;
    const int row0 = blockIdx.x * 128;
    const int warpM = (wid & 3) * 32;
    const int warpN = (wid >> 2) * 32;

    const int lrA = tid >> 1;
    const int cA  = (tid & 1) * 2;
    const int lrB = tid >> 2;
    const int cB  = tid & 3;

    const int l4 = lane & 15;
    const u32 aRowOff = (u32)((lane & 15) * PITCH + ((lane >> 4) << 4));
    const u32 bRowOff = (u32)((l4 & 7) * PITCH + ((l4 >> 3) << 4));

    const int NS = HID >> 5;

    if (blockIdx.y < 65) {
        const int col0 = (blockIdx.y - 1) * 64;

        auto load_stage = [&](int kt, int buf) {
            const u32 so = sb + buf * STG_GU;
            const size_t goA = (size_t)(row0 + lrA) * HID + kt * 32;
            cp16(so + lrA * PITCH + cA * 16,       Xh + goA + cA * 8);
            cp16(so + lrA * PITCH + (cA + 1) * 16, Xh + goA + (cA + 1) * 8);
            const size_t goB = (size_t)(col0 + lrB) * HID + kt * 32;
            cp16(so + PLANE128 + lrB * PITCH + cB * 16,            Wgh + goB + cB * 8);
            cp16(so + PLANE128 + PLANE64 + lrB * PITCH + cB * 16,  Wuh + goB + cB * 8);
        };

        float accG[2][4][4], accU[2][4][4];
        #pragma unroll
        for (int i = 0; i < 2; i++)
            #pragma unroll
            for (int j = 0; j < 4; j++)
                #pragma unroll
                for (int t = 0; t < 4; t++) { accG[i][j][t] = 0.f; accU[i][j][t] = 0.f; }

        load_stage(0, 0); CP_COMMIT();
        load_stage(1, 1); CP_COMMIT();

        for (int s = 0; s < NS; s++) {
            const int buf = s % 3;
            CP_WAIT(1);
            __syncthreads();
            if (s + 2 < NS) load_stage(s + 2, (s + 2) % 3);
            CP_COMMIT();

            const u32 stg = sb + buf * STG_GU;
            #pragma unroll
            for (int ks = 0; ks < 2; ks++) {
                const u32 kb = ks * 32;
                u32 ah[2][4], bg[4][2], bu[4][2];
                #pragma unroll
                for (int i = 0; i < 2; i++)
                    ldsm_x4(ah[i][0], ah[i][1], ah[i][2], ah[i][3],
                            stg + (warpM + i * 16) * PITCH + kb + aRowOff);
                #pragma unroll
                for (int j = 0; j < 4; j++) {
                    const u32 rb = stg + PLANE128 + (warpN + j * 8) * PITCH + kb + bRowOff;
                    ldsm_x2(bg[j][0], bg[j][1], rb);
                    ldsm_x2(bu[j][0], bu[j][1], rb + PLANE64);
                }
                #pragma unroll
                for (int i = 0; i < 2; i++)
                    #pragma unroll
                    for (int j = 0; j < 4; j++) {
                        mma_f32(accG[i][j], ah[i], bg[j]);
                        mma_f32(accU[i][j], ah[i], bu[j]);
                    }
            }
        }

        #pragma unroll
        for (int i = 0; i < 2; i++) {
            #pragma unroll
            for (int j = 0; j < 4; j++) {
                const int r = row0 + warpM + i * 16 + (lane >> 2);
                const int c = col0 + warpN + j * 8 + (lane & 3) * 2;
                #pragma unroll
                for (int half = 0; half < 2; half++) {
                    const int rr = r + half * 8;
                    const float gg0 = accG[i][j][half * 2 + 0];
                    const float gg1 = accG[i][j][half * 2 + 1];
                    const float uu0 = accU[i][j][half * 2 + 0];
                    const float uu1 = accU[i][j][half * 2 + 1];
                    __half2 hp = __halves2half2(__float2half_rn(silu(gg0) * uu0),
                                                __float2half_rn(silu(gg1) * uu1));
                    ((u32*)Hh)[((size_t)rr * INTER + c) >> 1] = *(u32*)&hp;
                }
            }
        }
    } else {
        const int col0 = (blockIdx.y - 65) * 64;

        auto load_stage = [&](int kt, int buf) {
            const u32 so = sb + buf * STG_R;
            const size_t goA = (size_t)(row0 + lrA) * HID + kt * 32;
            cp16(so + lrA * PITCH + cA * 16,                  Xh + goA + cA * 8);
            cp16(so + lrA * PITCH + (cA + 1) * 16,            Xh + goA + (cA + 1) * 8);
            cp16(so + PLANE128 + lrA * PITCH + cA * 16,       Xl + goA + cA * 8);
            cp16(so + PLANE128 + lrA * PITCH + (cA + 1) * 16, Xl + goA + (cA + 1) * 8);
            const size_t goB = (size_t)(col0 + lrB) * HID + kt * 32;
            cp16(so + 2 * PLANE128 + lrB * PITCH + cB * 16,           Wrh + goB + cB * 8);
            cp16(so + 2 * PLANE128 + PLANE64 + lrB * PITCH + cB * 16, Wrl + goB + cB * 8);
        };

        float acc[2][4][4];
        u32   accX[2][4][2];
        #pragma unroll
        for (int i = 0; i < 2; i++)
            #pragma unroll
            for (int j = 0; j < 4; j++) {
                #pragma unroll
                for (int t = 0; t < 4; t++) acc[i][j][t] = 0.f;
                accX[i][j][0] = 0u; accX[i][j][1] = 0u;
            }

        load_stage(0, 0); CP_COMMIT();

        for (int s = 0; s < NS; s++) {
            const int buf = s & 1;
            if (s + 1 < NS) load_stage(s + 1, (s + 1) & 1);
            CP_COMMIT();
            CP_WAIT(1);
            __syncthreads();

            const u32 stg = sb + buf * STG_R;
            #pragma unroll
            for (int ks = 0; ks < 2; ks++) {
                const u32 kb = ks * 32;
                u32 ah[2][4], al[2][4], bh[4][2], bl[4][2];
                #pragma unroll
                for (int i = 0; i < 2; i++) {
                    const u32 ra = stg + (warpM + i * 16) * PITCH + kb + aRowOff;
                    ldsm_x4(ah[i][0], ah[i][1], ah[i][2], ah[i][3], ra);
                    ldsm_x4(al[i][0], al[i][1], al[i][2], al[i][3], ra + PLANE128);
                }
                #pragma unroll
                for (int j = 0; j < 4; j++) {
                    const u32 rb = stg + 2 * PLANE128 + (warpN + j * 8) * PITCH + kb + bRowOff;
                    ldsm_x2(bh[j][0], bh[j][1], rb);
                    ldsm_x2(bl[j][0], bl[j][1], rb + PLANE64);
                }
                #pragma unroll
                for (int i = 0; i < 2; i++)
                    #pragma unroll
                    for (int j = 0; j < 4; j++) {
                        mma_f32(acc[i][j], ah[i], bh[j]);
                        mma_f16(accX[i][j], ah[i], bl[j]);
                        mma_f16(accX[i][j], al[i], bh[j]);
                    }
            }
            __syncthreads();
        }

        #pragma unroll
        for (int i = 0; i < 2; i++) {
            #pragma unroll
            for (int j = 0; j < 4; j++) {
                float2 x0 = __half22float2(*(__half2*)&accX[i][j][0]);
                float2 x1 = __half22float2(*(__half2*)&accX[i][j][1]);
                const float vv[4] = { acc[i][j][0] + x0.x, acc[i][j][1] + x0.y,
                                      acc[i][j][2] + x1.x, acc[i][j][3] + x1.y };
                const int r = row0 + warpM + i * 16 + (lane >> 2);
                const int c = col0 + warpN + j * 8 + (lane & 3) * 2;
                #pragma unroll
                for (int half = 0; half < 2; half++) {
                    const int rr = r + half * 8;
                    *(float2*)(logits + (size_t)rr * 128 + c) =
                        make_float2(vv[half * 2 + 0], vv[half * 2 + 1]);
                }
            }
        }
    }
}

// =====================================================================
// routing_kernel: grid 16 x 256 — top-8(x) x top-8(y) -> top-8 sums.
// =====================================================================
__device__ __forceinline__ void top8_insert(float v, int idx, float* hv, int* hi) {
    if (v <= hv[7]) return;
    int p = 7;
    #pragma unroll
    for (int q = 7; q > 0; q--) {
        if (v > hv[q-1]) { hv[q] = hv[q-1]; hi[q] = hi[q-1]; p = q - 1; }
    }
    hv[p] = v; hi[p] = idx;
}

__global__ void routing_kernel(const float* __restrict__ logits)
{
    const int m = blockIdx.x * 256 + threadIdx.x;
    const float* px = logits + (size_t)(m >> 1) * 128 + (m & 1) * 64;
    const float* py = logits + (size_t)(2048 + (m >> 1)) * 128 + (m & 1) * 64;

    float vx[8], vy[8];
    int   ix[8], iy[8];
    #pragma unroll
    for (int t = 0; t < 8; t++) { vx[t] = -3.4e38f; vy[t] = -3.4e38f; ix[t] = 0; iy[t] = 0; }
    for (int k = 0; k < NKEYS; k++) top8_insert(px[k], k, vx, ix);
    for (int k = 0; k < NKEYS; k++) top8_insert(py[k], k, vy, iy);

    float sv[8]; int sa[8];
    #pragma unroll
    for (int t = 0; t < 8; t++) { sv[t] = -3.4e38f; sa[t] = 0; }
    for (int a = 0; a < 8; a++)
        for (int bq = 0; bq < 8; bq++)
            top8_insert(vx[a] + vy[bq], a * 8 + bq, sv, sa);

    float mx = sv[0];
    float e[8], s = 0.f;
    #pragma unroll
    for (int t = 0; t < 8; t++) { e[t] = expf(sv[t] - mx); s += e[t]; }
    float w[8], s2 = 0.f;
    #pragma unroll
    for (int t = 0; t < 8; t++) { w[t] = e[t] / s; s2 += w[t]; }
    #pragma unroll
    for (int t = 0; t < 8; t++) w[t] /= s2;

    #pragma unroll
    for (int t = 0; t < 8; t++) {
        int a = sa[t] >> 3, bq = sa[t] & 7;
        g_tidx[m * TOPK + t] = ix[a] * NKEYS + iy[bq];
        g_tw[m * TOPK + t]   = w[t];
    }
}

// =====================================================================
// tail_kernel (R8-proven): grid 256 + 4096, occ 2.
//  bid < 256 : down GEMM tile (128x128, 4-stage, atomicAdd epilogue)
//  bid >= 256: experts token (atomicAdd epilogue), backfills idle slots.
// out pre-zeroed; each element gets EXACTLY two atomic adds -> deterministic.
// =====================================================================
#define STG1 20480                    // 2 x PLANE128
#define SMEM_TAIL (4 * STG1)          // 81920

__global__ __launch_bounds__(256, 2)
void tail_kernel(const u16* __restrict__ A_h, const u16* __restrict__ B_h,
                 float* __restrict__ out,
                 const float* __restrict__ X,
                 const float* __restrict__ down_e,
                 const float* __restrict__ up_e)
{
    extern __shared__ char sm[];
    const int tid  = threadIdx.x;

    if (blockIdx.x < 256) {
        const u32 sb = smem_u32(sm);
        const int lane = tid & 31;
        const int wid  = tid >> 5;
        const int row0 = (blockIdx.x & 31) * 128;
        const int col0 = (blockIdx.x >> 5) * 128;
        const int warpM = (wid >> 2) * 64;
        const int warpN = (wid & 3) * 32;
        const int K = INTER, ldC = HID;

        const int f  = tid * 2;
        const int lr = f >> 2;
        const int c0 = f & 3;

        const int NS = K >> 5;

        auto load_stage = [&](int kt, int buf) {
            const size_t goA = (size_t)(row0 + lr) * K + kt * 32;
            const size_t goB = (size_t)(col0 + lr) * K + kt * 32;
            const u32 so = sb + buf * STG1 + lr * PITCH;
            cp16(so + c0 * 16,                  A_h + goA + c0 * 8);
            cp16(so + (c0 + 1) * 16,            A_h + goA + (c0 + 1) * 8);
            cp16(so + PLANE128 + c0 * 16,       B_h + goB + c0 * 8);
            cp16(so + PLANE128 + (c0 + 1) * 16, B_h + goB + (c0 + 1) * 8);
        };

        float acc[4][4][4];
        #pragma unroll
        for (int i = 0; i < 4; i++)
            #pragma unroll
            for (int j = 0; j < 4; j++)
                #pragma unroll
                for (int t = 0; t < 4; t++) acc[i][j][t] = 0.f;

        const int l4 = lane & 15;
        const u32 aRowOff = (u32)((lane & 15) * PITCH + ((lane >> 4) << 4));
        const u32 bRowOff = (u32)((l4 & 7) * PITCH + ((l4 >> 3) << 4));

        load_stage(0, 0); CP_COMMIT();
        load_stage(1, 1); CP_COMMIT();
        load_stage(2, 2); CP_COMMIT();

        for (int s = 0; s < NS; s++) {
            const int buf = s & 3;
            CP_WAIT(2);
            __syncthreads();
            if (s + 3 < NS) load_stage(s + 3, (s + 3) & 3);
            CP_COMMIT();

            const u32 stg = sb + buf * STG1;
            #pragma unroll
            for (int ks = 0; ks < 2; ks++) {
                const u32 kb = ks * 32;
                u32 ah[4][4], bh[4][2];
                #pragma unroll
                for (int i = 0; i < 4; i++)
                    ldsm_x4(ah[i][0], ah[i][1], ah[i][2], ah[i][3],
                            stg + (warpM + i * 16) * PITCH + kb + aRowOff);
                #pragma unroll
                for (int j = 0; j < 4; j++)
                    ldsm_x2(bh[j][0], bh[j][1],
                            stg + PLANE128 + (warpN + j * 8) * PITCH + kb + bRowOff);
                #pragma unroll
                for (int i = 0; i < 4; i++)
                    #pragma unroll
                    for (int j = 0; j < 4; j++) mma_f32(acc[i][j], ah[i], bh[j]);
            }
        }

        #pragma unroll
        for (int i = 0; i < 4; i++) {
            #pragma unroll
            for (int j = 0; j < 4; j++) {
                const int r = row0 + warpM + i * 16 + (lane >> 2);
                const int c = col0 + warpN + j * 8 + (lane & 3) * 2;
                #pragma unroll
                for (int half = 0; half < 2; half++) {
                    const int rr = r + half * 8;
                    atomicAdd(out + (size_t)rr * ldC + c,     acc[i][j][half * 2 + 0]);
                    atomicAdd(out + (size_t)rr * ldC + c + 1, acc[i][j][half * 2 + 1]);
                }
            }
        }
    } else {
        const int m = blockIdx.x - 256;
        float4* xs4 = (float4*)sm;
        float*  ews = (float*)(sm + 4096);

        xs4[tid] = ((const float4*)(X + (size_t)m * HID))[tid];
        __syncthreads();

        const float* xs = (const float*)xs4;
        const int wid  = tid >> 5;
        const int lane = tid & 31;

        {
            int e = g_tidx[m * TOPK + wid];
            const float* d = down_e + (size_t)e * HID;
            float s = 0.f;
            for (int k = lane; k < HID; k += 32) s = fmaf(d[k], xs[k], s);
            #pragma unroll
            for (int o = 16; o; o >>= 1) s += __shfl_xor_sync(0xffffffffu, s, o);
            if (lane == 0) {
                float sig = s / (1.f + expf(-s));
                ews[wid] = sig * g_tw[m * TOPK + wid];
            }
        }
        __syncthreads();

        float4 acc = make_float4(0.f, 0.f, 0.f, 0.f);
        #pragma unroll
        for (int k = 0; k < TOPK; k++) {
            int e = g_tidx[m * TOPK + k];
            float w = ews[k];
            float4 u = ((const float4*)(up_e + (size_t)e * HID))[tid];
            acc.x = fmaf(w, u.x, acc.x);
            acc.y = fmaf(w, u.y, acc.y);
            acc.z = fmaf(w, u.z, acc.z);
            acc.w = fmaf(w, u.w, acc.w);
        }
        float* dst = out + (size_t)m * HID + tid * 4;
        atomicAdd(dst + 0, acc.x);
        atomicAdd(dst + 1, acc.y);
        atomicAdd(dst + 2, acc.z);
        atomicAdd(dst + 3, acc.w);
    }
}

// ---------------- launch ----------------
static void* sym(const void* s) { void* p = nullptr; cudaGetSymbolAddress(&p, s); return p; }

extern "C" void kernel_launch(void* const* d_in, const int* in_sizes, int n_in,
                              void* d_out, int out_size)
{
    const float* X        = (const float*)d_in[0];
    const float* w_gate   = (const float*)d_in[1];
    const float* w_up     = (const float*)d_in[2];
    const float* w_down   = (const float*)d_in[3];
    const float* w_router = (const float*)d_in[4];
    const float* down_e   = (const float*)d_in[5];
    const float* up_e     = (const float*)d_in[6];

    float* out    = (float*)d_out;
    float* logits = (float*)d_out + (size_t)NTOK * HID;

    u16 *Xh = (u16*)sym(g_Xh),  *Xl = (u16*)sym(g_Xl);
    u16 *Wgh = (u16*)sym(g_Wgh);
    u16 *Wuh = (u16*)sym(g_Wuh);
    u16 *Wdh = (u16*)sym(g_Wdh);
    u16 *Wrh = (u16*)sym(g_Wrh), *Wrl = (u16*)sym(g_Wrl);
    u16 *Hh = (u16*)sym(g_Hh);

    cudaFuncSetAttribute(mlp1_kernel, cudaFuncAttributeMaxDynamicSharedMemorySize, SMEM_MLP1);
    cudaFuncSetAttribute(tail_kernel, cudaFuncAttributeMaxDynamicSharedMemorySize, SMEM_TAIL);

    // 0) splits (X, Wr, Wg, Wu) + zero out, one launch
    split_all_kernel<<<16512, 256>>>(X, w_router, w_gate, w_up,
                                     Xh, Xl, Wrh, Wrl, Wgh, Wuh, out);
    // 1) fused gate/up + router + hidden Wd split (y=0, first wave)
    mlp1_kernel<<<dim3(NTOK / 128, 67), 256, SMEM_MLP1>>>(
        Xh, Xl, Wgh, Wuh, Wrh, Wrl, w_down, Wdh, Hh, logits);
    // 2) routing top-k
    routing_kernel<<<16, 256>>>(logits);
    // 3) down GEMM + experts (R8-proven tail)
    tail_kernel<<<256 + NTOK, 256, SMEM_TAIL>>>(Hh, Wdh, out, X, down_e, up_e);
    (void)in_sizes; (void)n_in; (void)out_size;
}